// round 5
// baseline (speedup 1.0000x reference)
#include <cuda_runtime.h>
#include <cuda_bf16.h>
#include <cstdint>

// ---------------------------------------------------------------------------
// MedianConvolution: out[n,c] = lower_median_k( (x @ W^T)[nbrs[n,k], c] )
// N=100000, K=32, IN_C=128, OUT_C=64.  nbrs is int32 (JAX demotes int64).
// ---------------------------------------------------------------------------

#define N_NODES 100000
#define IN_C    128
#define OUT_C   64
#define KNBR    32

// intermediate h = x @ W^T  (25.6 MB static device scratch — allocation-free)
__device__ float g_h[N_NODES * OUT_C];

// ---------------------------------------------------------------------------
// Kernel 1: h = x @ W^T.  One thread per node row, but x is staged through
// shared memory in K-chunks of 32 (coalesced float4 global loads, pad-33
// conflict-free scalar reads).  W lives in smem in native [c][k] layout and
// is read as float4 with warp-uniform addresses (broadcast).  FFMA-bound.
// ---------------------------------------------------------------------------
__global__ __launch_bounds__(256) void gemm_kernel(
    const float* __restrict__ x,
    const float* __restrict__ W,
    int n)
{
    __shared__ float wsh[OUT_C * IN_C];   // 32 KB, [c][k]
    __shared__ float xsh[256 * 33];       // ~33.8 KB, pad 33 -> conflict-free

    const int tid = threadIdx.x;
    const int rowBase = blockIdx.x * 256;
    const int r = rowBase + tid;

    for (int e = tid; e < OUT_C * IN_C; e += 256)
        wsh[e] = W[e];

    float acc[OUT_C];
#pragma unroll
    for (int c = 0; c < OUT_C; c++) acc[c] = 0.0f;

    for (int kb = 0; kb < 4; kb++) {      // K-chunks of 32
        __syncthreads();
        // stage x[rowBase..rowBase+255][kb*32 .. kb*32+31]: 2048 float4, 8/thread
#pragma unroll
        for (int i = 0; i < 8; i++) {
            int e   = tid + i * 256;      // 0..2047
            int row = e >> 3;             // 0..255
            int k4  = e & 7;              // 0..7
            int grow = rowBase + row;
            float4 v = make_float4(0.f, 0.f, 0.f, 0.f);
            if (grow < n)
                v = __ldg(reinterpret_cast<const float4*>(
                        x + (size_t)grow * IN_C + kb * 32) + k4);
            float* dst = &xsh[row * 33 + k4 * 4];
            dst[0] = v.x; dst[1] = v.y; dst[2] = v.z; dst[3] = v.w;
        }
        __syncthreads();

        const float*  xrow = &xsh[tid * 33];
        // w4[c*32 + kb*8 + j] = W[c][4*(kb*8+j) .. +3]
        const float4* w4 = reinterpret_cast<const float4*>(wsh);

#pragma unroll
        for (int j = 0; j < 8; j++) {
            const float x0 = xrow[j * 4 + 0];
            const float x1 = xrow[j * 4 + 1];
            const float x2 = xrow[j * 4 + 2];
            const float x3 = xrow[j * 4 + 3];
#pragma unroll
            for (int c = 0; c < OUT_C; c++) {
                const float4 w = w4[c * 32 + kb * 8 + j];  // warp-uniform
                acc[c] += x0 * w.x + x1 * w.y + x2 * w.z + x3 * w.w;
            }
        }
    }

    if (r < n) {
        float4* out4 = reinterpret_cast<float4*>(g_h + (size_t)r * OUT_C);
#pragma unroll
        for (int c4 = 0; c4 < OUT_C / 4; c4++)
            out4[c4] = make_float4(acc[4 * c4], acc[4 * c4 + 1],
                                   acc[4 * c4 + 2], acc[4 * c4 + 3]);
    }
}

// ---------------------------------------------------------------------------
// Kernel 2: gather + lower-median over K=32.
// 256 threads/block = 4 nodes x 64 channels; warp = 32 consecutive channels
// of one node -> each neighbor gather touches one 128B line (L2-resident).
// Median: Green's 60-comparator sort on each half of 16, then 16th-smallest
// of the merge via max_i min(A[i], B[15-i]).  271 min/max ops vs 351 before.
// ---------------------------------------------------------------------------
__device__ __forceinline__ void cas(float& a, float& b) {
    float lo = fminf(a, b);
    b = fmaxf(a, b);
    a = lo;
}

__device__ __forceinline__ void sort16g(float* v) {
    // Green's 60-comparator sorting network for 16 inputs (canonical listing)
    cas(v[0],v[1]);  cas(v[2],v[3]);  cas(v[4],v[5]);  cas(v[6],v[7]);
    cas(v[8],v[9]);  cas(v[10],v[11]);cas(v[12],v[13]);cas(v[14],v[15]);
    cas(v[0],v[2]);  cas(v[4],v[6]);  cas(v[8],v[10]); cas(v[12],v[14]);
    cas(v[1],v[3]);  cas(v[5],v[7]);  cas(v[9],v[11]); cas(v[13],v[15]);
    cas(v[0],v[4]);  cas(v[8],v[12]); cas(v[1],v[5]);  cas(v[9],v[13]);
    cas(v[2],v[6]);  cas(v[10],v[14]);cas(v[3],v[7]);  cas(v[11],v[15]);
    cas(v[0],v[8]);  cas(v[1],v[9]);  cas(v[2],v[10]); cas(v[3],v[11]);
    cas(v[4],v[12]); cas(v[5],v[13]); cas(v[6],v[14]); cas(v[7],v[15]);
    cas(v[5],v[10]); cas(v[6],v[9]);  cas(v[3],v[12]); cas(v[13],v[14]);
    cas(v[7],v[11]); cas(v[1],v[2]);  cas(v[4],v[8]);
    cas(v[1],v[4]);  cas(v[7],v[13]); cas(v[2],v[8]);  cas(v[11],v[14]);
    cas(v[2],v[4]);  cas(v[5],v[6]);  cas(v[9],v[10]); cas(v[11],v[13]);
    cas(v[3],v[8]);  cas(v[7],v[12]);
    cas(v[6],v[8]);  cas(v[10],v[12]);cas(v[3],v[5]);  cas(v[7],v[9]);
    cas(v[3],v[4]);  cas(v[5],v[6]);  cas(v[7],v[8]);  cas(v[9],v[10]);
    cas(v[11],v[12]);
    cas(v[6],v[7]);  cas(v[8],v[9]);
}

__global__ __launch_bounds__(256) void median_kernel(
    const int* __restrict__ nbrs,      // int32
    float* __restrict__ out,
    int n)
{
    __shared__ int snb[4 * KNBR];

    const int base = blockIdx.x * 4;
    const int tid = threadIdx.x;

    if (tid < 4 * KNBR) {
        int node = base + (tid >> 5);
        int idx = (node < n) ? nbrs[(size_t)node * KNBR + (tid & 31)] : 0;
        idx = max(0, min(idx, n - 1));   // defensive clamp
        snb[tid] = idx;
    }
    __syncthreads();

    const int ty = tid >> 6;   // node within block (0..3)
    const int tx = tid & 63;   // output channel
    const int node = base + ty;
    if (node >= n) return;

    float v[KNBR];
#pragma unroll
    for (int k = 0; k < KNBR; k++) {
        int idx = snb[ty * KNBR + k];            // smem broadcast
        v[k] = __ldg(&g_h[(size_t)idx * OUT_C + tx]);
    }

    sort16g(v);
    sort16g(v + 16);

    // 16th smallest (rank index 15) of the merge of two sorted 16-arrays
    float med = fminf(v[0], v[31]);
#pragma unroll
    for (int i = 1; i < 16; i++)
        med = fmaxf(med, fminf(v[i], v[31 - i]));

    out[(size_t)node * OUT_C + tx] = med;
}

// ---------------------------------------------------------------------------
extern "C" void kernel_launch(void* const* d_in, const int* in_sizes, int n_in,
                              void* d_out, int out_size) {
    const float* x    = (const float*)d_in[0];
    const int*   nbrs = (const int*)d_in[1];
    const float* W    = (const float*)d_in[2];
    float*       out  = (float*)d_out;

    const int n = in_sizes[0] / IN_C;   // 100000

    gemm_kernel<<<(n + 255) / 256, 256>>>(x, W, n);
    median_kernel<<<(n + 3) / 4, 256>>>(nbrs, out, n);
}